// round 11
// baseline (speedup 1.0000x reference)
#include <cuda_runtime.h>

// LinearActorNet: B=2048, K=512, N=256, T=64. task_id/action int32.
// out layout (float32): [action(B) | log_prob(B) | entropy(B)]
//
// 2-kernel deterministic pipeline:
//  1) logits: grid (64 tasks x 2 slots x 2 K-halves), 256 thr.
//     In-CTA ballot compaction of this task's sample list (no setup kernel).
//     Tile = 16 rows x 256 cols; thread = (row-group, col pair): 8 rows x
//     2 cols x 256 k, packed f32x2 FFMA. Partials to g_part[ks].
//  2) softmax: 256 CTAs x 8 rows; part0+part1+bias, fused log-softmax.

#define BB 2048
#define KK 512
#define NN 256
#define TT 64
#define TMR 16
#define NSLOT 2
#define KSPLIT 2
#define KH 256
#define LSTRIDE 128

__device__ float g_part[KSPLIT][BB][NN];

union f2u { float2 f; unsigned long long u; };
__device__ __forceinline__ unsigned long long pk(float lo, float hi) {
    f2u u; u.f = make_float2(lo, hi); return u.u;
}
__device__ __forceinline__ float fold(unsigned long long v) {
    f2u u; u.u = v; return u.f.x + u.f.y;
}
#define FFMA2(d, a, b) \
    asm("fma.rn.f32x2 %0, %1, %2, %0;" : "+l"(d) : "l"(a), "l"(b))

// ---------------- stage 1: compaction + split-K partial logits ----------------
__global__ __launch_bounds__(256, 3)
void logits_kernel(const float* __restrict__ xs,
                   const int* __restrict__ task_id,
                   const float* __restrict__ W)
{
    __shared__ float xs_s[TMR][KH];              // 16 KB
    __shared__ unsigned short lst[LSTRIDE];
    __shared__ int wcnt[8];

    const int tid  = threadIdx.x;
    const int t    = blockIdx.x;
    const int slot = blockIdx.y;
    const int ks   = blockIdx.z;
    const int lane = tid & 31;
    const int w    = tid >> 5;                   // warp 0..7
    const unsigned lt = (1u << lane) - 1u;

    // ---- in-CTA ballot compaction: this task's sample list ----
    int ids[8];
    #pragma unroll
    for (int i = 0; i < 8; i++)
        ids[i] = task_id[w * 256 + i * 32 + lane];
    int c = 0;
    #pragma unroll
    for (int i = 0; i < 8; i++)
        c += __popc(__ballot_sync(0xffffffffu, ids[i] == t));
    if (lane == 0) wcnt[w] = c;
    __syncthreads();
    int base = 0, cnt = 0;
    #pragma unroll
    for (int i = 0; i < 8; i++) {
        if (i < w) base += wcnt[i];
        cnt += wcnt[i];
    }
    cnt = min(cnt, LSTRIDE);
    #pragma unroll
    for (int i = 0; i < 8; i++) {
        bool p = (ids[i] == t);
        unsigned m = __ballot_sync(0xffffffffu, p);
        if (p) {
            int pos = base + __popc(m & lt);
            if (pos < LSTRIDE)
                lst[pos] = (unsigned short)(w * 256 + i * 32 + lane);
        }
        base += __popc(m);
    }
    __syncthreads();

    if (slot * TMR >= cnt) return;

    const int rg = tid >> 7;                     // row group: rows rg*8..rg*8+7
    const int cl = tid & 127;                    // owns cols cl, cl+128
    const float* __restrict__ Wt =
        W + (size_t)t * (KK * NN) + (size_t)ks * KH * NN + cl;

    for (int tile = slot; tile * TMR < cnt; tile += NSLOT) {
        const int m0 = tile * TMR;
        const int mc = min(TMR, cnt - m0);
        __syncthreads();

        // ---- stage xs tile [TMR][KH] (float4, coalesced) ----
        #pragma unroll
        for (int i = 0; i < (TMR * KH / 4) / 256; i++) {   // 4 iters
            int idx = i * 256 + tid;
            int m = idx >> 6;                              // 64 float4 per row
            int cc = idx & 63;
            float4 v = make_float4(0.f, 0.f, 0.f, 0.f);
            if (m < mc) {
                const float4* src =
                    (const float4*)(xs + (size_t)lst[m0 + m] * KK + ks * KH);
                v = src[cc];
            }
            *(float4*)&xs_s[m][cc * 4] = v;
        }
        __syncthreads();

        // ---- GEMM: 8 rows x 2 cols per thread, packed f32x2 ----
        unsigned long long acc0[8], acc1[8];
        #pragma unroll
        for (int m = 0; m < 8; m++) { acc0[m] = 0ull; acc1[m] = 0ull; }

        #pragma unroll 2
        for (int k = 0; k < KH; k += 4) {
            const float* wk = Wt + (size_t)k * NN;
            float a0 = wk[0],   a1 = wk[NN],     a2 = wk[2*NN],     a3 = wk[3*NN];
            float b0 = wk[128], b1 = wk[NN+128], b2 = wk[2*NN+128], b3 = wk[3*NN+128];
            unsigned long long wA0 = pk(a0, a1), wA1 = pk(a2, a3);
            unsigned long long wB0 = pk(b0, b1), wB1 = pk(b2, b3);
            #pragma unroll
            for (int m = 0; m < 8; m++) {
                ulonglong2 xv =
                    *(const ulonglong2*)&xs_s[rg * 8 + m][k];  // LDS.128 bcast
                FFMA2(acc0[m], xv.x, wA0);
                FFMA2(acc0[m], xv.y, wA1);
                FFMA2(acc1[m], xv.x, wB0);
                FFMA2(acc1[m], xv.y, wB1);
            }
        }

        // ---- store partials (coalesced) ----
        #pragma unroll
        for (int m = 0; m < 8; m++) {
            int r = rg * 8 + m;
            if (r < mc) {
                float* dst = &g_part[ks][lst[m0 + r]][0];
                dst[cl]       = fold(acc0[m]);
                dst[cl + 128] = fold(acc1[m]);
            }
        }
    }
}

// ---------------- stage 2: bias + fused log-softmax + outputs ----------------
#define RW 8
__global__ __launch_bounds__(256, 4)
void softmax_kernel(const int* __restrict__ task_id,
                    const int* __restrict__ action,
                    const float* __restrict__ bias,
                    float* __restrict__ out)
{
    __shared__ float redm[RW][8];
    __shared__ float reda[RW][8];
    __shared__ float redb[RW][8];

    const int tid  = threadIdx.x;           // column n = tid
    const int row0 = blockIdx.x * RW;
    const int lane = tid & 31;
    const int wid  = tid >> 5;

    float v[RW];
    #pragma unroll
    for (int r = 0; r < RW; r++) {
        const int row = row0 + r;
        const int t   = task_id[row];
        v[r] = g_part[0][row][tid] + g_part[1][row][tid] + bias[t * NN + tid];
    }

    float mx[RW];
    #pragma unroll
    for (int r = 0; r < RW; r++) {
        float x = v[r];
        #pragma unroll
        for (int o = 16; o > 0; o >>= 1)
            x = fmaxf(x, __shfl_xor_sync(0xffffffffu, x, o));
        if (lane == 0) redm[r][wid] = x;
    }
    __syncthreads();
    #pragma unroll
    for (int r = 0; r < RW; r++) {
        float x = redm[r][0];
        #pragma unroll
        for (int w = 1; w < 8; w++) x = fmaxf(x, redm[r][w]);
        mx[r] = x;
    }

    #pragma unroll
    for (int r = 0; r < RW; r++) {
        float d = v[r] - mx[r];
        float e = __expf(d);
        float s1 = e, s2 = e * d;
        #pragma unroll
        for (int o = 16; o > 0; o >>= 1) {
            s1 += __shfl_xor_sync(0xffffffffu, s1, o);
            s2 += __shfl_xor_sync(0xffffffffu, s2, o);
        }
        if (lane == 0) { reda[r][wid] = s1; redb[r][wid] = s2; }
    }
    __syncthreads();

    #pragma unroll
    for (int r = 0; r < RW; r++) {
        float s1 = 0.f, s2 = 0.f;
        #pragma unroll
        for (int w = 0; w < 8; w++) { s1 += reda[r][w]; s2 += redb[r][w]; }
        const int   row  = row0 + r;
        const int   a    = action[row];
        const float logS = logf(s1);
        if (tid == a)
            out[BB + row] = v[r] - mx[r] - logS;       // log_prob
        if (tid == 0) {
            out[row]          = (float)a;              // action (as float)
            out[2 * BB + row] = logS - s2 / s1;        // entropy
        }
    }
}

extern "C" void kernel_launch(void* const* d_in, const int* in_sizes, int n_in,
                              void* d_out, int out_size) {
    const float* xs      = (const float*)d_in[0];
    const int*   task_id = (const int*)d_in[1];
    const int*   action  = (const int*)d_in[2];
    const float* W       = (const float*)d_in[3];
    const float* bias    = (const float*)d_in[4];
    float*       out     = (float*)d_out;

    dim3 grid(TT, NSLOT, KSPLIT);
    logits_kernel<<<grid, 256>>>(xs, task_id, W);
    softmax_kernel<<<BB / RW, 256>>>(task_id, action, bias, out);
}

// round 13
// speedup vs baseline: 1.1449x; 1.1449x over previous
#include <cuda_runtime.h>

// LinearActorNet: B=2048, K=512, N=256, T=64. task_id/action int32.
// out layout (float32): [action(B) | log_prob(B) | entropy(B)]
//
// SINGLE fused kernel. Grid (64 tasks x 4 slots), 512 threads, DYNAMIC smem.
// - in-CTA ballot compaction of the task's sample list
// - thread = (K-half kh, row-group rg, col cl): 8 rows x 2 cols x 256 k,
//   packed f32x2 FFMA (in-CTA split-K doubles warps vs full-K threads)
// - halves combined in smem part_s; fused log-softmax epilogue (warps 0-7)

#define BB 2048
#define KK 512
#define NN 256
#define TT 64
#define TMR 16
#define NSLOT 4
#define NT 512
#define LSTRIDE 128

// dynamic smem layout (floats):
//  xs_s   : [TMR][KK]        = 8192 f   (32 KB)   offset 0
//  part_s : [2][TMR][NN]     = 8192 f   (32 KB)   offset 8192
//  bias_s : [NN]             = 256 f               offset 16384
//  lst    : [LSTRIDE] u16    = 64 f                offset 16640
//  wcnt   : [16] int         = 16 f                offset 16704
#define SMEM_FLOATS (16704 + 16)
#define SMEM_BYTES  (SMEM_FLOATS * 4)

union f2u { float2 f; unsigned long long u; };
__device__ __forceinline__ unsigned long long pk(float lo, float hi) {
    f2u u; u.f = make_float2(lo, hi); return u.u;
}
__device__ __forceinline__ float fold(unsigned long long v) {
    f2u u; u.u = v; return u.f.x + u.f.y;
}
#define FFMA2(d, a, b) \
    asm("fma.rn.f32x2 %0, %1, %2, %0;" : "+l"(d) : "l"(a), "l"(b))

extern __shared__ float smem_f[];

__global__ __launch_bounds__(NT, 1)
void actor_kernel(const float* __restrict__ xs,
                  const int* __restrict__ task_id,
                  const int* __restrict__ action,
                  const float* __restrict__ W,
                  const float* __restrict__ bias,
                  float* __restrict__ out)
{
    float (*xs_s)[KK]        = (float (*)[KK])(smem_f);
    float (*part_s)[TMR][NN] = (float (*)[TMR][NN])(smem_f + 8192);
    float* bias_s            = smem_f + 16384;
    unsigned short* lst      = (unsigned short*)(smem_f + 16640);
    int* wcnt                = (int*)(smem_f + 16704);

    const int tid  = threadIdx.x;
    const int t    = blockIdx.x;
    const int slot = blockIdx.y;
    const int lane = tid & 31;
    const int w    = tid >> 5;                   // warp 0..15
    const unsigned lt = (1u << lane) - 1u;

    // ---- in-CTA ballot compaction (16 warps x 4 rounds of 32) ----
    int ids[4];
    #pragma unroll
    for (int i = 0; i < 4; i++)
        ids[i] = task_id[w * 128 + i * 32 + lane];
    int c = 0;
    #pragma unroll
    for (int i = 0; i < 4; i++)
        c += __popc(__ballot_sync(0xffffffffu, ids[i] == t));
    if (lane == 0) wcnt[w] = c;
    if (tid < NN) bias_s[tid] = bias[t * NN + tid];
    __syncthreads();
    int base = 0, cnt = 0;
    #pragma unroll
    for (int i = 0; i < 16; i++) {
        if (i < w) base += wcnt[i];
        cnt += wcnt[i];
    }
    cnt = min(cnt, LSTRIDE);
    #pragma unroll
    for (int i = 0; i < 4; i++) {
        bool p = (ids[i] == t);
        unsigned m = __ballot_sync(0xffffffffu, p);
        if (p) {
            int pos = base + __popc(m & lt);
            if (pos < LSTRIDE)
                lst[pos] = (unsigned short)(w * 128 + i * 32 + lane);
        }
        base += __popc(m);
    }
    __syncthreads();

    if (slot * TMR >= cnt) return;

    const int kh  = tid >> 8;                    // K-half 0/1
    const int sub = tid & 255;
    const int rg  = sub >> 7;                    // rows rg*8 .. rg*8+7
    const int cl  = sub & 127;                   // cols cl, cl+128
    const float* __restrict__ Wt =
        W + (size_t)t * (KK * NN) + (size_t)kh * 256 * NN + cl;

    for (int tile = slot; tile * TMR < cnt; tile += NSLOT) {
        const int m0 = tile * TMR;
        const int mc = min(TMR, cnt - m0);
        __syncthreads();

        // ---- stage xs tile [TMR][KK] (float4, coalesced; 4/thread) ----
        #pragma unroll
        for (int i = 0; i < (TMR * KK / 4) / NT; i++) {   // 4 iters
            int idx = i * NT + tid;
            int m = idx >> 7;                             // 128 float4 per row
            int cc = idx & 127;
            float4 v = make_float4(0.f, 0.f, 0.f, 0.f);
            if (m < mc) {
                const float4* src =
                    (const float4*)(xs + (size_t)lst[m0 + m] * KK);
                v = src[cc];
            }
            *(float4*)&xs_s[m][cc * 4] = v;
        }
        __syncthreads();

        // ---- GEMM over K-half: 8 rows x 2 cols, packed f32x2 ----
        unsigned long long acc0[8], acc1[8];
        #pragma unroll
        for (int m = 0; m < 8; m++) { acc0[m] = 0ull; acc1[m] = 0ull; }

        #pragma unroll 2
        for (int k = 0; k < 256; k += 4) {
            const float* wk = Wt + (size_t)k * NN;
            float a0 = wk[0],   a1 = wk[NN],     a2 = wk[2*NN],     a3 = wk[3*NN];
            float b0 = wk[128], b1 = wk[NN+128], b2 = wk[2*NN+128], b3 = wk[3*NN+128];
            unsigned long long wA0 = pk(a0, a1), wA1 = pk(a2, a3);
            unsigned long long wB0 = pk(b0, b1), wB1 = pk(b2, b3);
            #pragma unroll
            for (int m = 0; m < 8; m++) {
                ulonglong2 xv =
                    *(const ulonglong2*)&xs_s[rg * 8 + m][kh * 256 + k];
                FFMA2(acc0[m], xv.x, wA0);
                FFMA2(acc0[m], xv.y, wA1);
                FFMA2(acc1[m], xv.x, wB0);
                FFMA2(acc1[m], xv.y, wB1);
            }
        }

        // ---- deposit partials in smem ----
        #pragma unroll
        for (int m = 0; m < 8; m++) {
            int r = rg * 8 + m;
            part_s[kh][r][cl]       = fold(acc0[m]);
            part_s[kh][r][cl + 128] = fold(acc1[m]);
        }
        __syncthreads();

        // ---- fused log-softmax epilogue: warps 0..7 -> rows 2w, 2w+1 ----
        if (w < 8) {
            #pragma unroll
            for (int rr = 0; rr < 2; rr++) {
                const int r = w * 2 + rr;
                if (r >= mc) break;
                const int gb = lst[m0 + r];
                const int a  = action[gb];

                float vr[8];
                #pragma unroll
                for (int j = 0; j < 8; j++) {
                    int cc = j * 32 + lane;
                    vr[j] = part_s[0][r][cc] + part_s[1][r][cc] + bias_s[cc];
                }
                float mx = vr[0];
                #pragma unroll
                for (int j = 1; j < 8; j++) mx = fmaxf(mx, vr[j]);
                #pragma unroll
                for (int o = 16; o > 0; o >>= 1)
                    mx = fmaxf(mx, __shfl_xor_sync(0xffffffffu, mx, o));

                float s1 = 0.f, s2 = 0.f, s3 = 0.f;
                #pragma unroll
                for (int j = 0; j < 8; j++) {
                    int cc = j * 32 + lane;
                    float d = vr[j] - mx;
                    float e = __expf(d);
                    s1 += e; s2 += e * d;
                    if (cc == a) s3 += vr[j];
                }
                #pragma unroll
                for (int o = 16; o > 0; o >>= 1) {
                    s1 += __shfl_xor_sync(0xffffffffu, s1, o);
                    s2 += __shfl_xor_sync(0xffffffffu, s2, o);
                    s3 += __shfl_xor_sync(0xffffffffu, s3, o);
                }
                if (lane == 0) {
                    float logS = logf(s1);
                    out[gb]          = (float)a;               // action
                    out[BB + gb]     = s3 - mx - logS;         // log_prob
                    out[2 * BB + gb] = logS - s2 / s1;         // entropy
                }
            }
        }
    }
}

extern "C" void kernel_launch(void* const* d_in, const int* in_sizes, int n_in,
                              void* d_out, int out_size) {
    const float* xs      = (const float*)d_in[0];
    const int*   task_id = (const int*)d_in[1];
    const int*   action  = (const int*)d_in[2];
    const float* W       = (const float*)d_in[3];
    const float* bias    = (const float*)d_in[4];
    float*       out     = (float*)d_out;

    static int configured = 0;
    if (!configured) {
        cudaFuncSetAttribute(actor_kernel,
                             cudaFuncAttributeMaxDynamicSharedMemorySize,
                             SMEM_BYTES);
        configured = 1;
    }

    dim3 grid(TT, NSLOT);
    actor_kernel<<<grid, NT, SMEM_BYTES>>>(xs, task_id, action, W, bias, out);
}

// round 14
// speedup vs baseline: 1.2728x; 1.1118x over previous
#include <cuda_runtime.h>

// LinearActorNet: B=2048, K=512, N=256, T=64. task_id/action int32.
// out layout (float32): [action(B) | log_prob(B) | entropy(B)]
//
// 2-kernel deterministic pipeline (no setup kernel, no atomics):
//  1) logits: grid (64 tasks x 2 slots x 4 K-quarters) = 512 CTAs, 256 thr.
//     In-CTA ballot compaction; tile 16 rows x 256 cols; thread =
//     (row-group, col pair): 8 rows x 2 cols x 128 k, packed f32x2 FFMA.
//  2) softmax: 512 CTAs x 4 rows; sum 4 partials + bias, fused log-softmax.

#define BB 2048
#define KK 512
#define NN 256
#define TT 64
#define TMR 16
#define NSLOT 2
#define KSPLIT 4
#define KH 128
#define LSTRIDE 128

__device__ float g_part[KSPLIT][BB][NN];

union f2u { float2 f; unsigned long long u; };
__device__ __forceinline__ unsigned long long pk(float lo, float hi) {
    f2u u; u.f = make_float2(lo, hi); return u.u;
}
__device__ __forceinline__ float fold(unsigned long long v) {
    f2u u; u.u = v; return u.f.x + u.f.y;
}
#define FFMA2(d, a, b) \
    asm("fma.rn.f32x2 %0, %1, %2, %0;" : "+l"(d) : "l"(a), "l"(b))

// ---------------- stage 1: compaction + split-K partial logits ----------------
__global__ __launch_bounds__(256, 3)
void logits_kernel(const float* __restrict__ xs,
                   const int* __restrict__ task_id,
                   const float* __restrict__ W)
{
    __shared__ float xs_s[TMR][KH];              // 8 KB
    __shared__ unsigned short lst[LSTRIDE];
    __shared__ int wcnt[8];

    const int tid  = threadIdx.x;
    const int t    = blockIdx.x;
    const int slot = blockIdx.y;
    const int ks   = blockIdx.z;
    const int lane = tid & 31;
    const int w    = tid >> 5;                   // warp 0..7
    const unsigned lt = (1u << lane) - 1u;

    // ---- in-CTA ballot compaction (8 warps x 8 rounds of 32) ----
    int ids[8];
    #pragma unroll
    for (int i = 0; i < 8; i++)
        ids[i] = task_id[w * 256 + i * 32 + lane];
    int c = 0;
    #pragma unroll
    for (int i = 0; i < 8; i++)
        c += __popc(__ballot_sync(0xffffffffu, ids[i] == t));
    if (lane == 0) wcnt[w] = c;
    __syncthreads();
    int base = 0, cnt = 0;
    #pragma unroll
    for (int i = 0; i < 8; i++) {
        if (i < w) base += wcnt[i];
        cnt += wcnt[i];
    }
    cnt = min(cnt, LSTRIDE);
    #pragma unroll
    for (int i = 0; i < 8; i++) {
        bool p = (ids[i] == t);
        unsigned m = __ballot_sync(0xffffffffu, p);
        if (p) {
            int pos = base + __popc(m & lt);
            if (pos < LSTRIDE)
                lst[pos] = (unsigned short)(w * 256 + i * 32 + lane);
        }
        base += __popc(m);
    }
    __syncthreads();

    if (slot * TMR >= cnt) return;

    const int rg = tid >> 7;                     // rows rg*8 .. rg*8+7
    const int cl = tid & 127;                    // cols cl, cl+128
    const float* __restrict__ Wt =
        W + (size_t)t * (KK * NN) + (size_t)ks * KH * NN + cl;

    for (int tile = slot; tile * TMR < cnt; tile += NSLOT) {
        const int m0 = tile * TMR;
        const int mc = min(TMR, cnt - m0);
        __syncthreads();

        // ---- stage xs tile [TMR][KH] (float4, coalesced) ----
        #pragma unroll
        for (int i = 0; i < (TMR * KH / 4) / 256; i++) {   // 2 iters
            int idx = i * 256 + tid;
            int m = idx >> 5;                              // 32 float4 per row
            int cc = idx & 31;
            float4 v = make_float4(0.f, 0.f, 0.f, 0.f);
            if (m < mc) {
                const float4* src =
                    (const float4*)(xs + (size_t)lst[m0 + m] * KK + ks * KH);
                v = src[cc];
            }
            *(float4*)&xs_s[m][cc * 4] = v;
        }
        __syncthreads();

        // ---- GEMM over K-quarter: 8 rows x 2 cols, packed f32x2 ----
        unsigned long long acc0[8], acc1[8];
        #pragma unroll
        for (int m = 0; m < 8; m++) { acc0[m] = 0ull; acc1[m] = 0ull; }

        #pragma unroll 4
        for (int k = 0; k < KH; k += 4) {
            const float* wk = Wt + (size_t)k * NN;
            float a0 = wk[0],   a1 = wk[NN],     a2 = wk[2*NN],     a3 = wk[3*NN];
            float b0 = wk[128], b1 = wk[NN+128], b2 = wk[2*NN+128], b3 = wk[3*NN+128];
            unsigned long long wA0 = pk(a0, a1), wA1 = pk(a2, a3);
            unsigned long long wB0 = pk(b0, b1), wB1 = pk(b2, b3);
            #pragma unroll
            for (int m = 0; m < 8; m++) {
                ulonglong2 xv =
                    *(const ulonglong2*)&xs_s[rg * 8 + m][k];  // LDS.128 bcast
                FFMA2(acc0[m], xv.x, wA0);
                FFMA2(acc0[m], xv.y, wA1);
                FFMA2(acc1[m], xv.x, wB0);
                FFMA2(acc1[m], xv.y, wB1);
            }
        }

        // ---- store partials (coalesced) ----
        #pragma unroll
        for (int m = 0; m < 8; m++) {
            int r = rg * 8 + m;
            if (r < mc) {
                float* dst = &g_part[ks][lst[m0 + r]][0];
                dst[cl]       = fold(acc0[m]);
                dst[cl + 128] = fold(acc1[m]);
            }
        }
    }
}

// ---------------- stage 2: bias + fused log-softmax + outputs ----------------
#define RW 4
__global__ __launch_bounds__(256, 6)
void softmax_kernel(const int* __restrict__ task_id,
                    const int* __restrict__ action,
                    const float* __restrict__ bias,
                    float* __restrict__ out)
{
    __shared__ float redm[RW][8];
    __shared__ float reda[RW][8];
    __shared__ float redb[RW][8];

    const int tid  = threadIdx.x;           // column n = tid
    const int row0 = blockIdx.x * RW;
    const int lane = tid & 31;
    const int wid  = tid >> 5;

    float v[RW];
    #pragma unroll
    for (int r = 0; r < RW; r++) {
        const int row = row0 + r;
        const int t   = task_id[row];
        v[r] = (g_part[0][row][tid] + g_part[1][row][tid])
             + (g_part[2][row][tid] + g_part[3][row][tid])
             + bias[t * NN + tid];
    }

    float mx[RW];
    #pragma unroll
    for (int r = 0; r < RW; r++) {
        float x = v[r];
        #pragma unroll
        for (int o = 16; o > 0; o >>= 1)
            x = fmaxf(x, __shfl_xor_sync(0xffffffffu, x, o));
        if (lane == 0) redm[r][wid] = x;
    }
    __syncthreads();
    #pragma unroll
    for (int r = 0; r < RW; r++) {
        float x = redm[r][0];
        #pragma unroll
        for (int w = 1; w < 8; w++) x = fmaxf(x, redm[r][w]);
        mx[r] = x;
    }

    #pragma unroll
    for (int r = 0; r < RW; r++) {
        float d = v[r] - mx[r];
        float e = __expf(d);
        float s1 = e, s2 = e * d;
        #pragma unroll
        for (int o = 16; o > 0; o >>= 1) {
            s1 += __shfl_xor_sync(0xffffffffu, s1, o);
            s2 += __shfl_xor_sync(0xffffffffu, s2, o);
        }
        if (lane == 0) { reda[r][wid] = s1; redb[r][wid] = s2; }
    }
    __syncthreads();

    #pragma unroll
    for (int r = 0; r < RW; r++) {
        float s1 = 0.f, s2 = 0.f;
        #pragma unroll
        for (int w = 0; w < 8; w++) { s1 += reda[r][w]; s2 += redb[r][w]; }
        const int   row  = row0 + r;
        const int   a    = action[row];
        const float logS = logf(s1);
        if (tid == a)
            out[BB + row] = v[r] - mx[r] - logS;       // log_prob
        if (tid == 0) {
            out[row]          = (float)a;              // action (as float)
            out[2 * BB + row] = logS - s2 / s1;        // entropy
        }
    }
}

extern "C" void kernel_launch(void* const* d_in, const int* in_sizes, int n_in,
                              void* d_out, int out_size) {
    const float* xs      = (const float*)d_in[0];
    const int*   task_id = (const int*)d_in[1];
    const int*   action  = (const int*)d_in[2];
    const float* W       = (const float*)d_in[3];
    const float* bias    = (const float*)d_in[4];
    float*       out     = (float*)d_out;

    dim3 grid(TT, NSLOT, KSPLIT);
    logits_kernel<<<grid, 256>>>(xs, task_id, W);
    softmax_kernel<<<BB / RW, 256>>>(task_id, action, bias, out);
}

// round 15
// speedup vs baseline: 1.4995x; 1.1781x over previous
#include <cuda_runtime.h>

// LinearActorNet: B=2048, K=512, N=256, T=64. task_id/action int32.
// out layout (float32): [action(B) | log_prob(B) | entropy(B)]
//
// 3-stage deterministic pipeline:
//  1) setup:  64 CTAs x 256 thr, register-cached ballot compaction (once).
//  2) logits: grid (64 tasks x 4 slots x 4 K-quarters), 256 thr, TMR=16,
//     thread = (row-group, col pair): 8 rows x 2 cols x 128 k.
//     Explicit depth-2 register double-buffer on the W stream (A/B sets)
//     so 8 LDGs are always in flight under the FFMA2 block.
//  3) softmax: 1024 CTAs x 2 rows; sum 4 partials + bias, fused log-softmax.

#define BB 2048
#define KK 512
#define NN 256
#define TT 64
#define TMR 16
#define NSLOT 4
#define KSPLIT 4
#define KH 128
#define LSTRIDE 128

__device__ unsigned short g_list[TT * LSTRIDE];
__device__ int g_cnt[TT];
__device__ float g_part[KSPLIT][BB][NN];

union f2u { float2 f; unsigned long long u; };
__device__ __forceinline__ unsigned long long pk(float lo, float hi) {
    f2u u; u.f = make_float2(lo, hi); return u.u;
}
__device__ __forceinline__ float fold(unsigned long long v) {
    f2u u; u.u = v; return u.f.x + u.f.y;
}
#define FFMA2(d, a, b) \
    asm("fma.rn.f32x2 %0, %1, %2, %0;" : "+l"(d) : "l"(a), "l"(b))

// ---------------- setup: per-task parallel compaction ----------------
__global__ __launch_bounds__(256, 4)
void setup_kernel(const int* __restrict__ task_id)
{
    const int t    = blockIdx.x;
    const int lane = threadIdx.x & 31;
    const int w    = threadIdx.x >> 5;          // 0..7
    const unsigned lt = (1u << lane) - 1u;
    __shared__ int wcnt[8];

    int ids[8];
    #pragma unroll
    for (int i = 0; i < 8; i++)
        ids[i] = task_id[w * 256 + i * 32 + lane];

    int c = 0;
    #pragma unroll
    for (int i = 0; i < 8; i++)
        c += __popc(__ballot_sync(0xffffffffu, ids[i] == t));
    if (lane == 0) wcnt[w] = c;
    __syncthreads();
    int base = 0;
    #pragma unroll
    for (int i = 0; i < 8; i++) if (i < w) base += wcnt[i];
    if (w == 7 && lane == 0) g_cnt[t] = base + wcnt[7];

    #pragma unroll
    for (int i = 0; i < 8; i++) {
        bool p = (ids[i] == t);
        unsigned m = __ballot_sync(0xffffffffu, p);
        if (p) {
            int pos = base + __popc(m & lt);
            if (pos < LSTRIDE)
                g_list[t * LSTRIDE + pos] =
                    (unsigned short)(w * 256 + i * 32 + lane);
        }
        base += __popc(m);
    }
}

// ---------------- stage 1: split-K partial logits (pipelined W) ----------------
#define LOADW(d, p) do {                                              \
    const float* _wk = (p);                                           \
    d##0 = _wk[0];    d##1 = _wk[NN];     d##2 = _wk[2*NN];   d##3 = _wk[3*NN];   \
    d##4 = _wk[128];  d##5 = _wk[NN+128]; d##6 = _wk[2*NN+128]; d##7 = _wk[3*NN+128]; \
} while (0)

#define FMABLK(d, kk) do {                                            \
    unsigned long long wA0 = pk(d##0, d##1), wA1 = pk(d##2, d##3);    \
    unsigned long long wB0 = pk(d##4, d##5), wB1 = pk(d##6, d##7);    \
    _Pragma("unroll")                                                 \
    for (int m = 0; m < 8; m++) {                                     \
        ulonglong2 xv = *(const ulonglong2*)&xs_s[rg * 8 + m][kk];    \
        FFMA2(acc0[m], xv.x, wA0);                                    \
        FFMA2(acc0[m], xv.y, wA1);                                    \
        FFMA2(acc1[m], xv.x, wB0);                                    \
        FFMA2(acc1[m], xv.y, wB1);                                    \
    }                                                                 \
} while (0)

__global__ __launch_bounds__(256, 3)
void logits_kernel(const float* __restrict__ xs,
                   const float* __restrict__ W)
{
    __shared__ float xs_s[TMR][KH];              // 8 KB

    const int tid  = threadIdx.x;
    const int t    = blockIdx.x;
    const int slot = blockIdx.y;
    const int ks   = blockIdx.z;

    const int cnt = min(g_cnt[t], LSTRIDE);
    if (slot * TMR >= cnt) return;
    const unsigned short* __restrict__ lst = g_list + t * LSTRIDE;

    const int rg = tid >> 7;                     // rows rg*8 .. rg*8+7
    const int cl = tid & 127;                    // cols cl, cl+128
    const float* __restrict__ Wt =
        W + (size_t)t * (KK * NN) + (size_t)ks * KH * NN + cl;

    for (int tile = slot; tile * TMR < cnt; tile += NSLOT) {
        const int m0 = tile * TMR;
        const int mc = min(TMR, cnt - m0);
        __syncthreads();

        // ---- stage xs tile [TMR][KH] (float4, coalesced) ----
        #pragma unroll
        for (int i = 0; i < (TMR * KH / 4) / 256; i++) {   // 2 iters
            int idx = i * 256 + tid;
            int m = idx >> 5;                              // 32 float4 per row
            int cc = idx & 31;
            float4 v = make_float4(0.f, 0.f, 0.f, 0.f);
            if (m < mc) {
                const float4* src =
                    (const float4*)(xs + (size_t)lst[m0 + m] * KK + ks * KH);
                v = src[cc];
            }
            *(float4*)&xs_s[m][cc * 4] = v;
        }
        __syncthreads();

        // ---- GEMM, depth-2 register double-buffer on W ----
        unsigned long long acc0[8], acc1[8];
        #pragma unroll
        for (int m = 0; m < 8; m++) { acc0[m] = 0ull; acc1[m] = 0ull; }

        float A0, A1, A2, A3, A4, A5, A6, A7;
        float B0, B1, B2, B3, B4, B5, B6, B7;
        LOADW(A, Wt);
        #pragma unroll
        for (int k = 0; k < KH; k += 8) {
            LOADW(B, Wt + (size_t)(k + 4) * NN);           // prefetch
            FMABLK(A, k);
            if (k + 8 < KH) LOADW(A, Wt + (size_t)(k + 8) * NN);
            FMABLK(B, k + 4);
        }

        // ---- store partials (coalesced) ----
        #pragma unroll
        for (int m = 0; m < 8; m++) {
            int r = rg * 8 + m;
            if (r < mc) {
                float* dst = &g_part[ks][lst[m0 + r]][0];
                dst[cl]       = fold(acc0[m]);
                dst[cl + 128] = fold(acc1[m]);
            }
        }
    }
}

// ---------------- stage 2: bias + fused log-softmax + outputs ----------------
#define RW 2
__global__ __launch_bounds__(256, 6)
void softmax_kernel(const int* __restrict__ task_id,
                    const int* __restrict__ action,
                    const float* __restrict__ bias,
                    float* __restrict__ out)
{
    __shared__ float redm[RW][8];
    __shared__ float reda[RW][8];
    __shared__ float redb[RW][8];

    const int tid  = threadIdx.x;           // column n = tid
    const int row0 = blockIdx.x * RW;
    const int lane = tid & 31;
    const int wid  = tid >> 5;

    float v[RW];
    #pragma unroll
    for (int r = 0; r < RW; r++) {
        const int row = row0 + r;
        const int t   = task_id[row];
        v[r] = (g_part[0][row][tid] + g_part[1][row][tid])
             + (g_part[2][row][tid] + g_part[3][row][tid])
             + bias[t * NN + tid];
    }

    float mx[RW];
    #pragma unroll
    for (int r = 0; r < RW; r++) {
        float x = v[r];
        #pragma unroll
        for (int o = 16; o > 0; o >>= 1)
            x = fmaxf(x, __shfl_xor_sync(0xffffffffu, x, o));
        if (lane == 0) redm[r][wid] = x;
    }
    __syncthreads();
    #pragma unroll
    for (int r = 0; r < RW; r++) {
        float x = redm[r][0];
        #pragma unroll
        for (int w = 1; w < 8; w++) x = fmaxf(x, redm[r][w]);
        mx[r] = x;
    }

    #pragma unroll
    for (int r = 0; r < RW; r++) {
        float d = v[r] - mx[r];
        float e = __expf(d);
        float s1 = e, s2 = e * d;
        #pragma unroll
        for (int o = 16; o > 0; o >>= 1) {
            s1 += __shfl_xor_sync(0xffffffffu, s1, o);
            s2 += __shfl_xor_sync(0xffffffffu, s2, o);
        }
        if (lane == 0) { reda[r][wid] = s1; redb[r][wid] = s2; }
    }
    __syncthreads();

    #pragma unroll
    for (int r = 0; r < RW; r++) {
        float s1 = 0.f, s2 = 0.f;
        #pragma unroll
        for (int w = 0; w < 8; w++) { s1 += reda[r][w]; s2 += redb[r][w]; }
        const int   row  = row0 + r;
        const int   a    = action[row];
        const float logS = logf(s1);
        if (tid == a)
            out[BB + row] = v[r] - mx[r] - logS;       // log_prob
        if (tid == 0) {
            out[row]          = (float)a;              // action (as float)
            out[2 * BB + row] = logS - s2 / s1;        // entropy
        }
    }
}

extern "C" void kernel_launch(void* const* d_in, const int* in_sizes, int n_in,
                              void* d_out, int out_size) {
    const float* xs      = (const float*)d_in[0];
    const int*   task_id = (const int*)d_in[1];
    const int*   action  = (const int*)d_in[2];
    const float* W       = (const float*)d_in[3];
    const float* bias    = (const float*)d_in[4];
    float*       out     = (float*)d_out;

    setup_kernel<<<TT, 256>>>(task_id);
    dim3 grid(TT, NSLOT, KSPLIT);
    logits_kernel<<<grid, 256>>>(xs, W);
    softmax_kernel<<<BB / RW, 256>>>(task_id, action, bias, out);
}